// round 6
// baseline (speedup 1.0000x reference)
#include <cuda_runtime.h>

#define TB 32
#define NT 256
#define XS 132
#define HS 264
#define SMEM_FLOATS 28704

__device__ __forceinline__ float sgm(float z){ return 1.0f/(1.0f + __expf(-z)); }

__global__ void __launch_bounds__(NT, 2)
ga_kernel(const float* __restrict__ gx,  const float* __restrict__ g_wr,
          const float* __restrict__ g_an,const float* __restrict__ g_wgp,
          const float* __restrict__ g_wl,const float* __restrict__ g_bl,
          const float* __restrict__ g_wu,const float* __restrict__ g_bu,
          const float* __restrict__ g_aa,const float* __restrict__ g_ba,
          const float* __restrict__ g_wd,const float* __restrict__ g_bd,
          float* __restrict__ gout, int Btot)
{
    extern __shared__ float sm[];
    float* xs   = sm;                 // [32][132]
    float* xrs  = xs  + TB*XS;        // [32][132]
    float* atts = xrs + TB*XS;        // [32][132]
    float* wr   = atts+ TB*XS;        // [n][g][16m] 1024
    float* wl   = wr  + 1024;         // 1024
    float* wgp  = wl  + 1024;         // [n][p][16m] 5120
    float* wu   = wgp + 5120;         // [m][g][64u] 4096
    float* wd   = wu  + 4096;         // [u][g][16m] 4096
    float* sn   = wd  + 4096;         // 64
    float* aa   = sn  + 64;           // 256
    float* ba   = aa  + 256;          // 256
    float* blv  = ba  + 256;          // 16
    float* buv  = blv + 16;           // 64
    float* bdv  = buv + 64;           // 16
    float* hs   = xs;                 // alias (x/xr dead in MLP phase)

    const int t = threadIdx.x;
    for (int i=t;i<1024;i+=NT){int m=i>>6,n=(i>>2)&15,g=i&3;int d=(n*4+g)*16+m;wr[d]=g_wr[i];wl[d]=g_wl[i];}
    for (int i=t;i<5120;i+=NT){int m=i/320,n=(i/20)%16,p=i%20;wgp[(n*20+p)*16+m]=g_wgp[i];}
    for (int i=t;i<4096;i+=NT){int u=i>>6,m=(i>>2)&15,g=i&3;wu[(m*4+g)*64+u]=g_wu[i];}
    for (int i=t;i<4096;i+=NT){int m=i>>8,u=(i>>2)&63,g=i&3;wd[(u*4+g)*16+m]=g_wd[i];}
    for (int i=t;i<64;i+=NT){sn[i]=sgm(g_an[i]);buv[i]=g_bu[i];}
    for (int i=t;i<256;i+=NT){aa[i]=g_aa[i];ba[i]=g_ba[i];}
    if (t<16){blv[t]=g_bl[t];bdv[t]=g_bd[t];}

    const int b0 = blockIdx.x * TB;
    for (int i=t;i<TB*32;i+=NT){
        int r=i>>5,c=i&31;
        if (b0+r<Btot) *(float4*)&xs[r*XS+c*4] = ((const float4*)gx)[(size_t)(b0+r)*32+c];
    }
    __syncthreads();

    const int bb = t>>3, q = t&7;
    const bool act = (b0+bb) < Btot;
    const float* xrow = &xs[bb*XS];
    const float* yrow = &xrs[bb*XS];

    // ---------------- Stage A: xr = norm(linear_right(x)) ----------------
    {
        float acc[2][8];
        #pragma unroll
        for(int c=0;c<2;c++)
            #pragma unroll
            for(int j=0;j<8;j++) acc[c][j]=0.f;
        #pragma unroll 4
        for (int n=0;n<16;n++){
            float4 xl=*(const float4*)&xrow[n*8];
            float4 xh=*(const float4*)&xrow[n*8+4];
            float2 w0=*(const float2*)&wr[(n*4+0)*16+2*q];
            float2 w1=*(const float2*)&wr[(n*4+1)*16+2*q];
            float2 w2=*(const float2*)&wr[(n*4+2)*16+2*q];
            float2 w3=*(const float2*)&wr[(n*4+3)*16+2*q];
            acc[0][0]=fmaf(xl.x,w0.x,acc[0][0]); acc[1][0]=fmaf(xl.x,w0.y,acc[1][0]);
            acc[0][1]=fmaf(xl.y,w1.x,acc[0][1]); acc[1][1]=fmaf(xl.y,w1.y,acc[1][1]);
            acc[0][2]=fmaf(xl.z,w1.x,acc[0][2]); acc[1][2]=fmaf(xl.z,w1.y,acc[1][2]);
            acc[0][3]=fmaf(xl.w,w1.x,acc[0][3]); acc[1][3]=fmaf(xl.w,w1.y,acc[1][3]);
            acc[0][4]=fmaf(xh.x,w2.x,acc[0][4]); acc[1][4]=fmaf(xh.x,w2.y,acc[1][4]);
            acc[0][5]=fmaf(xh.y,w2.x,acc[0][5]); acc[1][5]=fmaf(xh.y,w2.y,acc[1][5]);
            acc[0][6]=fmaf(xh.z,w2.x,acc[0][6]); acc[1][6]=fmaf(xh.z,w2.y,acc[1][6]);
            acc[0][7]=fmaf(xh.w,w3.x,acc[0][7]); acc[1][7]=fmaf(xh.w,w3.y,acc[1][7]);
        }
        #pragma unroll
        for (int c=0;c<2;c++){
            int mm=2*q+c;
            float n0=fabsf(acc[c][0]);
            float n1=sqrtf(acc[c][1]*acc[c][1]+acc[c][2]*acc[c][2]+acc[c][3]*acc[c][3]);
            float n2=sqrtf(acc[c][4]*acc[c][4]+acc[c][5]*acc[c][5]+acc[c][6]*acc[c][6]);
            float n3=fabsf(acc[c][7]);
            float r0=1.f/(fmaf(sn[mm*4+0],n0-1.f,1.f)+1e-6f);
            float r1=1.f/(fmaf(sn[mm*4+1],n1-1.f,1.f)+1e-6f);
            float r2=1.f/(fmaf(sn[mm*4+2],n2-1.f,1.f)+1e-6f);
            float r3=1.f/(fmaf(sn[mm*4+3],n3-1.f,1.f)+1e-6f);
            *(float4*)&xrs[bb*XS+mm*8]   = make_float4(acc[c][0]*r0,acc[c][1]*r1,acc[c][2]*r1,acc[c][3]*r1);
            *(float4*)&xrs[bb*XS+mm*8+4] = make_float4(acc[c][4]*r2,acc[c][5]*r2,acc[c][6]*r2,acc[c][7]*r3);
        }
    }
    __syncthreads();

    // ------- Stage B: attended = (linear_left(x)+b_left + GP(x,xr))/sqrt2 -------
    {
        float at[2][8];
        #pragma unroll
        for(int c=0;c<2;c++){
            at[c][0]=blv[2*q+c];
            #pragma unroll
            for(int j=1;j<8;j++) at[c][j]=0.f;
        }
        #pragma unroll 2
        for (int n=0;n<16;n++){
            float4 xl=*(const float4*)&xrow[n*8];
            float4 xh=*(const float4*)&xrow[n*8+4];
            float4 yl=*(const float4*)&yrow[n*8];
            float4 yh=*(const float4*)&yrow[n*8+4];
            float x0=xl.x,x1=xl.y,x2=xl.z,x3=xl.w,x4=xh.x,x5=xh.y,x6=xh.z,x7=xh.w;
            float y0=yl.x,y1=yl.y,y2=yl.z,y3=yl.w,y4=yh.x,y5=yh.y,y6=yh.z,y7=yh.w;
            // left linear
            {
                float2 l0=*(const float2*)&wl[(n*4+0)*16+2*q];
                float2 l1=*(const float2*)&wl[(n*4+1)*16+2*q];
                float2 l2=*(const float2*)&wl[(n*4+2)*16+2*q];
                float2 l3=*(const float2*)&wl[(n*4+3)*16+2*q];
                at[0][0]=fmaf(x0,l0.x,at[0][0]); at[1][0]=fmaf(x0,l0.y,at[1][0]);
                at[0][1]=fmaf(x1,l1.x,at[0][1]); at[1][1]=fmaf(x1,l1.y,at[1][1]);
                at[0][2]=fmaf(x2,l1.x,at[0][2]); at[1][2]=fmaf(x2,l1.y,at[1][2]);
                at[0][3]=fmaf(x3,l1.x,at[0][3]); at[1][3]=fmaf(x3,l1.y,at[1][3]);
                at[0][4]=fmaf(x4,l2.x,at[0][4]); at[1][4]=fmaf(x4,l2.y,at[1][4]);
                at[0][5]=fmaf(x5,l2.x,at[0][5]); at[1][5]=fmaf(x5,l2.y,at[1][5]);
                at[0][6]=fmaf(x6,l2.x,at[0][6]); at[1][6]=fmaf(x6,l2.y,at[1][6]);
                at[0][7]=fmaf(x7,l3.x,at[0][7]); at[1][7]=fmaf(x7,l3.y,at[1][7]);
            }
            // Cayley buckets (44 nonzero (path, out-blade) terms of Cl(3,0))
            float a0=x0*y0,a1=x0*y1,a2=x0*y2,a3=x0*y3,a4=x0*y4,a5=x0*y5,a6=x0*y6,a7=x0*y7;
            float c1=x1*y0,c2=x2*y0,c3=x3*y0,c4=x4*y0,c5=x5*y0,c6=x6*y0,c7=x7*y0;
            float p4b = fmaf(x1,y1,fmaf(x2,y2,x3*y3));
            float p10b=-fmaf(x4,y4,fmaf(x5,y5,x6*y6));
            float p16b=-x7*y7;
            float q1=-fmaf(x2,y4, x3*y5);
            float q2= fmaf(x1,y4,-x3*y6);
            float q3= fmaf(x1,y5, x2*y6);
            float r1= fmaf(x4,y2, x5*y3);
            float r2= fmaf(x6,y3,-x4*y1);
            float r3=-fmaf(x5,y1, x6*y2);
            float s1=-x6*y7, s2= x5*y7, s3=-x4*y7;
            float t1=-x7*y6, t2= x7*y5, t3=-x7*y4;
            float u4= fmaf(x1,y2,-x2*y1);
            float u5= fmaf(x1,y3,-x3*y1);
            float u6= fmaf(x2,y3,-x3*y2);
            float v4= x3*y7, v5=-x2*y7, v6= x1*y7;
            float e4= x7*y3, e5=-x7*y2, e6= x7*y1;
            float m4= fmaf(x6,y5,-x5*y6);
            float m5= fmaf(x4,y6,-x6*y4);
            float m6= fmaf(x5,y4,-x4*y5);
            float z7a=fmaf(x1,y6,fmaf(-x2,y5,x3*y4));
            float z7b=fmaf(x4,y3,fmaf(-x5,y2,x6*y1));
            #pragma unroll
            for(int c=0;c<2;c++){
                const float* W = &wgp[n*320 + 2*q + c];
                float W0=W[0],W1=W[16],W2=W[32],W3=W[48],W4=W[64],W5=W[80],W6=W[96],
                      W7=W[112],W8=W[128],W9=W[144],W10=W[160],W11=W[176],W12=W[192],
                      W13=W[208],W14=W[224],W15=W[240],W16=W[256],W17=W[272],W18=W[288],W19=W[304];
                at[c][0]=fmaf(W0,a0,fmaf(W4,p4b,fmaf(W10,p10b,fmaf(W16,p16b,at[c][0]))));
                at[c][1]=fmaf(W1,a1,fmaf(W5,c1,fmaf(W6,q1,fmaf(W11,r1,fmaf(W12,s1,fmaf(W17,t1,at[c][1]))))));
                at[c][2]=fmaf(W1,a2,fmaf(W5,c2,fmaf(W6,q2,fmaf(W11,r2,fmaf(W12,s2,fmaf(W17,t2,at[c][2]))))));
                at[c][3]=fmaf(W1,a3,fmaf(W5,c3,fmaf(W6,q3,fmaf(W11,r3,fmaf(W12,s3,fmaf(W17,t3,at[c][3]))))));
                at[c][4]=fmaf(W2,a4,fmaf(W13,c4,fmaf(W7,u4,fmaf(W8,v4,fmaf(W18,e4,fmaf(W14,m4,at[c][4]))))));
                at[c][5]=fmaf(W2,a5,fmaf(W13,c5,fmaf(W7,u5,fmaf(W8,v5,fmaf(W18,e5,fmaf(W14,m5,at[c][5]))))));
                at[c][6]=fmaf(W2,a6,fmaf(W13,c6,fmaf(W7,u6,fmaf(W8,v6,fmaf(W18,e6,fmaf(W14,m6,at[c][6]))))));
                at[c][7]=fmaf(W3,a7,fmaf(W19,c7,fmaf(W9,z7a,fmaf(W15,z7b,at[c][7]))));
            }
        }
        const float RS2=0.70710678118654752440f;
        #pragma unroll
        for(int c=0;c<2;c++){
            int mm=2*q+c;
            *(float4*)&atts[bb*XS+mm*8]   = make_float4(at[c][0]*RS2,at[c][1]*RS2,at[c][2]*RS2,at[c][3]*RS2);
            *(float4*)&atts[bb*XS+mm*8+4] = make_float4(at[c][4]*RS2,at[c][5]*RS2,at[c][6]*RS2,at[c][7]*RS2);
        }
    }
    __syncthreads();

    // ---------------- Stage C: MLP (up -> gate -> down) in 2 u-passes ----------------
    float oacc[2][8];
    #pragma unroll
    for(int c=0;c<2;c++){
        oacc[c][0]=bdv[2*q+c];
        #pragma unroll
        for(int j=1;j<8;j++) oacc[c][j]=0.f;
    }
    const float* arow=&atts[bb*XS];
    #pragma unroll
    for (int pass=0;pass<2;pass++){
        const int u0 = pass*32 + q*4;
        float h[4][8];
        #pragma unroll
        for(int uu=0;uu<4;uu++){
            h[uu][0]=buv[u0+uu];
            #pragma unroll
            for(int j=1;j<8;j++) h[uu][j]=0.f;
        }
        #pragma unroll 4
        for (int m=0;m<16;m++){
            float4 al=*(const float4*)&arow[m*8];
            float4 ah=*(const float4*)&arow[m*8+4];
            float4 w0=*(const float4*)&wu[(m*4+0)*64+u0];
            float4 w1=*(const float4*)&wu[(m*4+1)*64+u0];
            float4 w2=*(const float4*)&wu[(m*4+2)*64+u0];
            float4 w3=*(const float4*)&wu[(m*4+3)*64+u0];
            float g0[4]={w0.x,w0.y,w0.z,w0.w};
            float g1[4]={w1.x,w1.y,w1.z,w1.w};
            float g2[4]={w2.x,w2.y,w2.z,w2.w};
            float g3[4]={w3.x,w3.y,w3.z,w3.w};
            #pragma unroll
            for(int uu=0;uu<4;uu++){
                h[uu][0]=fmaf(al.x,g0[uu],h[uu][0]);
                h[uu][1]=fmaf(al.y,g1[uu],h[uu][1]);
                h[uu][2]=fmaf(al.z,g1[uu],h[uu][2]);
                h[uu][3]=fmaf(al.w,g1[uu],h[uu][3]);
                h[uu][4]=fmaf(ah.x,g2[uu],h[uu][4]);
                h[uu][5]=fmaf(ah.y,g2[uu],h[uu][5]);
                h[uu][6]=fmaf(ah.z,g2[uu],h[uu][6]);
                h[uu][7]=fmaf(ah.w,g3[uu],h[uu][7]);
            }
        }
        #pragma unroll
        for(int uu=0;uu<4;uu++){
            int u=u0+uu;
            float i0=h[uu][0];
            float i1=fmaf(h[uu][1],h[uu][1],fmaf(h[uu][2],h[uu][2],h[uu][3]*h[uu][3]));
            float i2=fmaf(h[uu][4],h[uu][4],fmaf(h[uu][5],h[uu][5],h[uu][6]*h[uu][6]));
            float i3=h[uu][7]*h[uu][7];
            float ga=sgm(fmaf(aa[u*4+0],i0,ba[u*4+0]));
            float gb=sgm(fmaf(aa[u*4+1],i1,ba[u*4+1]));
            float gc=sgm(fmaf(aa[u*4+2],i2,ba[u*4+2]));
            float gd=sgm(fmaf(aa[u*4+3],i3,ba[u*4+3]));
            int slot=uu*8+q;
            *(float4*)&hs[bb*HS+slot*8]   = make_float4(h[uu][0]*ga,h[uu][1]*gb,h[uu][2]*gb,h[uu][3]*gb);
            *(float4*)&hs[bb*HS+slot*8+4] = make_float4(h[uu][4]*gc,h[uu][5]*gc,h[uu][6]*gc,h[uu][7]*gd);
        }
        __syncthreads();
        #pragma unroll 4
        for (int s=0;s<32;s++){
            int u = pass*32 + ((s&7)<<2) + (s>>3);
            float4 hl=*(const float4*)&hs[bb*HS+s*8];
            float4 hh=*(const float4*)&hs[bb*HS+s*8+4];
            float2 w0=*(const float2*)&wd[(u*4+0)*16+2*q];
            float2 w1=*(const float2*)&wd[(u*4+1)*16+2*q];
            float2 w2=*(const float2*)&wd[(u*4+2)*16+2*q];
            float2 w3=*(const float2*)&wd[(u*4+3)*16+2*q];
            oacc[0][0]=fmaf(hl.x,w0.x,oacc[0][0]); oacc[1][0]=fmaf(hl.x,w0.y,oacc[1][0]);
            oacc[0][1]=fmaf(hl.y,w1.x,oacc[0][1]); oacc[1][1]=fmaf(hl.y,w1.y,oacc[1][1]);
            oacc[0][2]=fmaf(hl.z,w1.x,oacc[0][2]); oacc[1][2]=fmaf(hl.z,w1.y,oacc[1][2]);
            oacc[0][3]=fmaf(hl.w,w1.x,oacc[0][3]); oacc[1][3]=fmaf(hl.w,w1.y,oacc[1][3]);
            oacc[0][4]=fmaf(hh.x,w2.x,oacc[0][4]); oacc[1][4]=fmaf(hh.x,w2.y,oacc[1][4]);
            oacc[0][5]=fmaf(hh.y,w2.x,oacc[0][5]); oacc[1][5]=fmaf(hh.y,w2.y,oacc[1][5]);
            oacc[0][6]=fmaf(hh.z,w2.x,oacc[0][6]); oacc[1][6]=fmaf(hh.z,w2.y,oacc[1][6]);
            oacc[0][7]=fmaf(hh.w,w3.x,oacc[0][7]); oacc[1][7]=fmaf(hh.w,w3.y,oacc[1][7]);
        }
        __syncthreads();
    }

    if (act){
        #pragma unroll
        for(int c=0;c<2;c++){
            int mm=2*q+c;
            float4 al=*(const float4*)&arow[mm*8];
            float4 ah=*(const float4*)&arow[mm*8+4];
            size_t o=(size_t)(b0+bb)*128 + mm*8;
            *(float4*)&gout[o]   = make_float4(al.x+oacc[c][0],al.y+oacc[c][1],al.z+oacc[c][2],al.w+oacc[c][3]);
            *(float4*)&gout[o+4] = make_float4(ah.x+oacc[c][4],ah.y+oacc[c][5],ah.z+oacc[c][6],ah.w+oacc[c][7]);
        }
    }
}

extern "C" void kernel_launch(void* const* d_in, const int* in_sizes, int n_in,
                              void* d_out, int out_size)
{
    const float* x    = (const float*)d_in[0];
    const float* wr   = (const float*)d_in[1];
    const float* an   = (const float*)d_in[2];
    const float* wgp  = (const float*)d_in[3];
    const float* wl   = (const float*)d_in[4];
    const float* bl   = (const float*)d_in[5];
    const float* wu   = (const float*)d_in[6];
    const float* bu   = (const float*)d_in[7];
    const float* aact = (const float*)d_in[8];
    const float* bact = (const float*)d_in[9];
    const float* wd   = (const float*)d_in[10];
    const float* bd   = (const float*)d_in[11];

    int Btot = in_sizes[0] / 128;
    int grid = (Btot + TB - 1) / TB;
    size_t smem = SMEM_FLOATS * sizeof(float);
    cudaFuncSetAttribute(ga_kernel, cudaFuncAttributeMaxDynamicSharedMemorySize, (int)smem);
    ga_kernel<<<grid, NT, smem>>>(x, wr, an, wgp, wl, bl, wu, bu, aact, bact, wd, bd,
                                  (float*)d_out, Btot);
}

// round 7
// speedup vs baseline: 1.0369x; 1.0369x over previous
#include <cuda_runtime.h>

#define TB 32
#define NT 256
#define XS 132
#define HS 264
#define SMEM_FLOATS 28704

__device__ __forceinline__ float sgm(float z){ return 1.0f/(1.0f + __expf(-z)); }

__global__ void __launch_bounds__(NT, 2)
ga_kernel(const float* __restrict__ gx,  const float* __restrict__ g_wr,
          const float* __restrict__ g_an,const float* __restrict__ g_wgp,
          const float* __restrict__ g_wl,const float* __restrict__ g_bl,
          const float* __restrict__ g_wu,const float* __restrict__ g_bu,
          const float* __restrict__ g_aa,const float* __restrict__ g_ba,
          const float* __restrict__ g_wd,const float* __restrict__ g_bd,
          float* __restrict__ gout, int Btot)
{
    extern __shared__ float sm[];
    float* xs   = sm;                 // [32][132]
    float* xrs  = xs  + TB*XS;
    float* atts = xrs + TB*XS;
    float* wr   = atts+ TB*XS;        // [n][slot][4g] 1024
    float* wl   = wr  + 1024;         // 1024
    float* wgp  = wl  + 1024;         // [n][5pg][slot][4p] 5120
    float* wu   = wgp + 5120;         // [m][g][64u] 4096
    float* wd   = wu  + 4096;         // [u][slot][4g] 4096
    float* sn   = wd  + 4096;         // 64
    float* aa   = sn  + 64;           // 256
    float* ba   = aa  + 256;          // 256
    float* blv  = ba  + 256;          // 16
    float* buv  = blv + 16;           // 64
    float* bdv  = buv + 64;           // 16
    float* hs   = xs;                 // alias (x/xr dead in MLP phase)

    const int t = threadIdx.x;
    // slot(m) = (m>>1) | ((m&1)<<3): even m -> slots 0..7, odd m -> slots 8..15
    for (int i=t;i<1024;i+=NT){
        int m=i>>6,n=(i>>2)&15,g=i&3;
        int sl=(m>>1)|((m&1)<<3);
        int d=(n*16+sl)*4+g;
        wr[d]=g_wr[i]; wl[d]=g_wl[i];
    }
    for (int i=t;i<5120;i+=NT){
        int m=i/320,n=(i/20)%16,p=i%20;
        int sl=(m>>1)|((m&1)<<3);
        wgp[((n*5+(p>>2))*16+sl)*4+(p&3)]=g_wgp[i];
    }
    for (int i=t;i<4096;i+=NT){int u=i>>6,m=(i>>2)&15,g=i&3;wu[(m*4+g)*64+u]=g_wu[i];}
    for (int i=t;i<4096;i+=NT){
        int m=i>>8,u=(i>>2)&63,g=i&3;
        int sl=(m>>1)|((m&1)<<3);
        wd[(u*16+sl)*4+g]=g_wd[i];
    }
    for (int i=t;i<64;i+=NT){sn[i]=sgm(g_an[i]);buv[i]=g_bu[i];}
    for (int i=t;i<256;i+=NT){aa[i]=g_aa[i];ba[i]=g_ba[i];}
    if (t<16){blv[t]=g_bl[t];bdv[t]=g_bd[t];}

    const int b0 = blockIdx.x * TB;
    for (int i=t;i<TB*32;i+=NT){
        int r=i>>5,c=i&31;
        if (b0+r<Btot) *(float4*)&xs[r*XS+c*4] = ((const float4*)gx)[(size_t)(b0+r)*32+c];
    }
    __syncthreads();

    const int bb = t>>3, q = t&7;
    const bool act = (b0+bb) < Btot;
    const float* xrow = &xs[bb*XS];
    const float* yrow = &xrs[bb*XS];

    // ---------------- Stage A: xr = norm(linear_right(x)) ----------------
    {
        float acc[2][8];
        #pragma unroll
        for(int c=0;c<2;c++)
            #pragma unroll
            for(int j=0;j<8;j++) acc[c][j]=0.f;
        #pragma unroll 4
        for (int n=0;n<16;n++){
            float4 xl=*(const float4*)&xrow[n*8];
            float4 xh=*(const float4*)&xrow[n*8+4];
            float4 w0=*(const float4*)&wr[(n*16+q)*4];      // m=2q   : g0..g3
            float4 w1=*(const float4*)&wr[(n*16+q+8)*4];    // m=2q+1 : g0..g3
            acc[0][0]=fmaf(xl.x,w0.x,acc[0][0]); acc[1][0]=fmaf(xl.x,w1.x,acc[1][0]);
            acc[0][1]=fmaf(xl.y,w0.y,acc[0][1]); acc[1][1]=fmaf(xl.y,w1.y,acc[1][1]);
            acc[0][2]=fmaf(xl.z,w0.y,acc[0][2]); acc[1][2]=fmaf(xl.z,w1.y,acc[1][2]);
            acc[0][3]=fmaf(xl.w,w0.y,acc[0][3]); acc[1][3]=fmaf(xl.w,w1.y,acc[1][3]);
            acc[0][4]=fmaf(xh.x,w0.z,acc[0][4]); acc[1][4]=fmaf(xh.x,w1.z,acc[1][4]);
            acc[0][5]=fmaf(xh.y,w0.z,acc[0][5]); acc[1][5]=fmaf(xh.y,w1.z,acc[1][5]);
            acc[0][6]=fmaf(xh.z,w0.z,acc[0][6]); acc[1][6]=fmaf(xh.z,w1.z,acc[1][6]);
            acc[0][7]=fmaf(xh.w,w0.w,acc[0][7]); acc[1][7]=fmaf(xh.w,w1.w,acc[1][7]);
        }
        #pragma unroll
        for (int c=0;c<2;c++){
            int mm=2*q+c;
            float n0=fabsf(acc[c][0]);
            float n1=sqrtf(acc[c][1]*acc[c][1]+acc[c][2]*acc[c][2]+acc[c][3]*acc[c][3]);
            float n2=sqrtf(acc[c][4]*acc[c][4]+acc[c][5]*acc[c][5]+acc[c][6]*acc[c][6]);
            float n3=fabsf(acc[c][7]);
            float r0=1.f/(fmaf(sn[mm*4+0],n0-1.f,1.f)+1e-6f);
            float r1=1.f/(fmaf(sn[mm*4+1],n1-1.f,1.f)+1e-6f);
            float r2=1.f/(fmaf(sn[mm*4+2],n2-1.f,1.f)+1e-6f);
            float r3=1.f/(fmaf(sn[mm*4+3],n3-1.f,1.f)+1e-6f);
            *(float4*)&xrs[bb*XS+mm*8]   = make_float4(acc[c][0]*r0,acc[c][1]*r1,acc[c][2]*r1,acc[c][3]*r1);
            *(float4*)&xrs[bb*XS+mm*8+4] = make_float4(acc[c][4]*r2,acc[c][5]*r2,acc[c][6]*r2,acc[c][7]*r3);
        }
    }
    __syncthreads();

    // ------- Stage B: attended = (linear_left(x)+b_left + GP(x,xr))/sqrt2 -------
    {
        float at[2][8];
        #pragma unroll
        for(int c=0;c<2;c++){
            at[c][0]=blv[2*q+c];
            #pragma unroll
            for(int j=1;j<8;j++) at[c][j]=0.f;
        }
        #pragma unroll 2
        for (int n=0;n<16;n++){
            float4 xl=*(const float4*)&xrow[n*8];
            float4 xh=*(const float4*)&xrow[n*8+4];
            float4 yl=*(const float4*)&yrow[n*8];
            float4 yh=*(const float4*)&yrow[n*8+4];
            float x0=xl.x,x1=xl.y,x2=xl.z,x3=xl.w,x4=xh.x,x5=xh.y,x6=xh.z,x7=xh.w;
            float y0=yl.x,y1=yl.y,y2=yl.z,y3=yl.w,y4=yh.x,y5=yh.y,y6=yh.z,y7=yh.w;
            // left linear
            {
                float4 l0=*(const float4*)&wl[(n*16+q)*4];
                float4 l1=*(const float4*)&wl[(n*16+q+8)*4];
                at[0][0]=fmaf(x0,l0.x,at[0][0]); at[1][0]=fmaf(x0,l1.x,at[1][0]);
                at[0][1]=fmaf(x1,l0.y,at[0][1]); at[1][1]=fmaf(x1,l1.y,at[1][1]);
                at[0][2]=fmaf(x2,l0.y,at[0][2]); at[1][2]=fmaf(x2,l1.y,at[1][2]);
                at[0][3]=fmaf(x3,l0.y,at[0][3]); at[1][3]=fmaf(x3,l1.y,at[1][3]);
                at[0][4]=fmaf(x4,l0.z,at[0][4]); at[1][4]=fmaf(x4,l1.z,at[1][4]);
                at[0][5]=fmaf(x5,l0.z,at[0][5]); at[1][5]=fmaf(x5,l1.z,at[1][5]);
                at[0][6]=fmaf(x6,l0.z,at[0][6]); at[1][6]=fmaf(x6,l1.z,at[1][6]);
                at[0][7]=fmaf(x7,l0.w,at[0][7]); at[1][7]=fmaf(x7,l1.w,at[1][7]);
            }
            // Cayley buckets (44 nonzero (path, out-blade) terms of Cl(3,0))
            float a0=x0*y0,a1=x0*y1,a2=x0*y2,a3=x0*y3,a4=x0*y4,a5=x0*y5,a6=x0*y6,a7=x0*y7;
            float c1=x1*y0,c2=x2*y0,c3=x3*y0,c4=x4*y0,c5=x5*y0,c6=x6*y0,c7=x7*y0;
            float p4b = fmaf(x1,y1,fmaf(x2,y2,x3*y3));
            float p10b=-fmaf(x4,y4,fmaf(x5,y5,x6*y6));
            float p16b=-x7*y7;
            float q1=-fmaf(x2,y4, x3*y5);
            float q2= fmaf(x1,y4,-x3*y6);
            float q3= fmaf(x1,y5, x2*y6);
            float r1= fmaf(x4,y2, x5*y3);
            float r2= fmaf(x6,y3,-x4*y1);
            float r3=-fmaf(x5,y1, x6*y2);
            float s1=-x6*y7, s2= x5*y7, s3=-x4*y7;
            float t1=-x7*y6, t2= x7*y5, t3=-x7*y4;
            float u4= fmaf(x1,y2,-x2*y1);
            float u5= fmaf(x1,y3,-x3*y1);
            float u6= fmaf(x2,y3,-x3*y2);
            float v4= x3*y7, v5=-x2*y7, v6= x1*y7;
            float e4= x7*y3, e5=-x7*y2, e6= x7*y1;
            float m4= fmaf(x6,y5,-x5*y6);
            float m5= fmaf(x4,y6,-x6*y4);
            float m6= fmaf(x5,y4,-x4*y5);
            float z7a=fmaf(x1,y6,fmaf(-x2,y5,x3*y4));
            float z7b=fmaf(x4,y3,fmaf(-x5,y2,x6*y1));
            #pragma unroll
            for(int c=0;c<2;c++){
                const int sl = q + 8*c;
                // W0..W19 packed as 5 float4 groups: Wp = P[p>>2][p&3]
                float4 P0=*(const float4*)&wgp[((n*5+0)*16+sl)*4];
                float4 P1=*(const float4*)&wgp[((n*5+1)*16+sl)*4];
                float4 P2=*(const float4*)&wgp[((n*5+2)*16+sl)*4];
                float4 P3=*(const float4*)&wgp[((n*5+3)*16+sl)*4];
                float4 P4=*(const float4*)&wgp[((n*5+4)*16+sl)*4];
                at[c][0]=fmaf(P0.x,a0,fmaf(P1.x,p4b,fmaf(P2.z,p10b,fmaf(P4.x,p16b,at[c][0]))));
                at[c][1]=fmaf(P0.y,a1,fmaf(P1.y,c1,fmaf(P1.z,q1,fmaf(P2.w,r1,fmaf(P3.x,s1,fmaf(P4.y,t1,at[c][1]))))));
                at[c][2]=fmaf(P0.y,a2,fmaf(P1.y,c2,fmaf(P1.z,q2,fmaf(P2.w,r2,fmaf(P3.x,s2,fmaf(P4.y,t2,at[c][2]))))));
                at[c][3]=fmaf(P0.y,a3,fmaf(P1.y,c3,fmaf(P1.z,q3,fmaf(P2.w,r3,fmaf(P3.x,s3,fmaf(P4.y,t3,at[c][3]))))));
                at[c][4]=fmaf(P0.z,a4,fmaf(P3.y,c4,fmaf(P1.w,u4,fmaf(P2.x,v4,fmaf(P4.z,e4,fmaf(P3.z,m4,at[c][4]))))));
                at[c][5]=fmaf(P0.z,a5,fmaf(P3.y,c5,fmaf(P1.w,u5,fmaf(P2.x,v5,fmaf(P4.z,e5,fmaf(P3.z,m5,at[c][5]))))));
                at[c][6]=fmaf(P0.z,a6,fmaf(P3.y,c6,fmaf(P1.w,u6,fmaf(P2.x,v6,fmaf(P4.z,e6,fmaf(P3.z,m6,at[c][6]))))));
                at[c][7]=fmaf(P0.w,a7,fmaf(P4.w,c7,fmaf(P2.y,z7a,fmaf(P3.w,z7b,at[c][7]))));
            }
        }
        const float RS2=0.70710678118654752440f;
        #pragma unroll
        for(int c=0;c<2;c++){
            int mm=2*q+c;
            *(float4*)&atts[bb*XS+mm*8]   = make_float4(at[c][0]*RS2,at[c][1]*RS2,at[c][2]*RS2,at[c][3]*RS2);
            *(float4*)&atts[bb*XS+mm*8+4] = make_float4(at[c][4]*RS2,at[c][5]*RS2,at[c][6]*RS2,at[c][7]*RS2);
        }
    }
    __syncthreads();

    // ---------------- Stage C: MLP (up -> gate -> down) in 2 u-passes ----------------
    float oacc[2][8];
    #pragma unroll
    for(int c=0;c<2;c++){
        oacc[c][0]=bdv[2*q+c];
        #pragma unroll
        for(int j=1;j<8;j++) oacc[c][j]=0.f;
    }
    const float* arow=&atts[bb*XS];
    #pragma unroll
    for (int pass=0;pass<2;pass++){
        const int u0 = pass*32 + q*4;
        float h[4][8];
        #pragma unroll
        for(int uu=0;uu<4;uu++){
            h[uu][0]=buv[u0+uu];
            #pragma unroll
            for(int j=1;j<8;j++) h[uu][j]=0.f;
        }
        #pragma unroll 4
        for (int m=0;m<16;m++){
            float4 al=*(const float4*)&arow[m*8];
            float4 ah=*(const float4*)&arow[m*8+4];
            float4 w0=*(const float4*)&wu[(m*4+0)*64+u0];
            float4 w1=*(const float4*)&wu[(m*4+1)*64+u0];
            float4 w2=*(const float4*)&wu[(m*4+2)*64+u0];
            float4 w3=*(const float4*)&wu[(m*4+3)*64+u0];
            float g0[4]={w0.x,w0.y,w0.z,w0.w};
            float g1[4]={w1.x,w1.y,w1.z,w1.w};
            float g2[4]={w2.x,w2.y,w2.z,w2.w};
            float g3[4]={w3.x,w3.y,w3.z,w3.w};
            #pragma unroll
            for(int uu=0;uu<4;uu++){
                h[uu][0]=fmaf(al.x,g0[uu],h[uu][0]);
                h[uu][1]=fmaf(al.y,g1[uu],h[uu][1]);
                h[uu][2]=fmaf(al.z,g1[uu],h[uu][2]);
                h[uu][3]=fmaf(al.w,g1[uu],h[uu][3]);
                h[uu][4]=fmaf(ah.x,g2[uu],h[uu][4]);
                h[uu][5]=fmaf(ah.y,g2[uu],h[uu][5]);
                h[uu][6]=fmaf(ah.z,g2[uu],h[uu][6]);
                h[uu][7]=fmaf(ah.w,g3[uu],h[uu][7]);
            }
        }
        #pragma unroll
        for(int uu=0;uu<4;uu++){
            int u=u0+uu;
            float i0=h[uu][0];
            float i1=fmaf(h[uu][1],h[uu][1],fmaf(h[uu][2],h[uu][2],h[uu][3]*h[uu][3]));
            float i2=fmaf(h[uu][4],h[uu][4],fmaf(h[uu][5],h[uu][5],h[uu][6]*h[uu][6]));
            float i3=h[uu][7]*h[uu][7];
            float ga=sgm(fmaf(aa[u*4+0],i0,ba[u*4+0]));
            float gb=sgm(fmaf(aa[u*4+1],i1,ba[u*4+1]));
            float gc=sgm(fmaf(aa[u*4+2],i2,ba[u*4+2]));
            float gd=sgm(fmaf(aa[u*4+3],i3,ba[u*4+3]));
            int slot=uu*8+q;
            *(float4*)&hs[bb*HS+slot*8]   = make_float4(h[uu][0]*ga,h[uu][1]*gb,h[uu][2]*gb,h[uu][3]*gb);
            *(float4*)&hs[bb*HS+slot*8+4] = make_float4(h[uu][4]*gc,h[uu][5]*gc,h[uu][6]*gc,h[uu][7]*gd);
        }
        __syncthreads();
        #pragma unroll 4
        for (int s=0;s<32;s++){
            int u = pass*32 + ((s&7)<<2) + (s>>3);
            float4 hl=*(const float4*)&hs[bb*HS+s*8];
            float4 hh=*(const float4*)&hs[bb*HS+s*8+4];
            float4 d0=*(const float4*)&wd[(u*16+q)*4];      // m=2q   : g0..g3
            float4 d1=*(const float4*)&wd[(u*16+q+8)*4];    // m=2q+1 : g0..g3
            oacc[0][0]=fmaf(hl.x,d0.x,oacc[0][0]); oacc[1][0]=fmaf(hl.x,d1.x,oacc[1][0]);
            oacc[0][1]=fmaf(hl.y,d0.y,oacc[0][1]); oacc[1][1]=fmaf(hl.y,d1.y,oacc[1][1]);
            oacc[0][2]=fmaf(hl.z,d0.y,oacc[0][2]); oacc[1][2]=fmaf(hl.z,d1.y,oacc[1][2]);
            oacc[0][3]=fmaf(hl.w,d0.y,oacc[0][3]); oacc[1][3]=fmaf(hl.w,d1.y,oacc[1][3]);
            oacc[0][4]=fmaf(hh.x,d0.z,oacc[0][4]); oacc[1][4]=fmaf(hh.x,d1.z,oacc[1][4]);
            oacc[0][5]=fmaf(hh.y,d0.z,oacc[0][5]); oacc[1][5]=fmaf(hh.y,d1.z,oacc[1][5]);
            oacc[0][6]=fmaf(hh.z,d0.z,oacc[0][6]); oacc[1][6]=fmaf(hh.z,d1.z,oacc[1][6]);
            oacc[0][7]=fmaf(hh.w,d0.w,oacc[0][7]); oacc[1][7]=fmaf(hh.w,d1.w,oacc[1][7]);
        }
        __syncthreads();
    }

    if (act){
        #pragma unroll
        for(int c=0;c<2;c++){
            int mm=2*q+c;
            float4 al=*(const float4*)&arow[mm*8];
            float4 ah=*(const float4*)&arow[mm*8+4];
            size_t o=(size_t)(b0+bb)*128 + mm*8;
            *(float4*)&gout[o]   = make_float4(al.x+oacc[c][0],al.y+oacc[c][1],al.z+oacc[c][2],al.w+oacc[c][3]);
            *(float4*)&gout[o+4] = make_float4(ah.x+oacc[c][4],ah.y+oacc[c][5],ah.z+oacc[c][6],ah.w+oacc[c][7]);
        }
    }
}

extern "C" void kernel_launch(void* const* d_in, const int* in_sizes, int n_in,
                              void* d_out, int out_size)
{
    const float* x    = (const float*)d_in[0];
    const float* wr   = (const float*)d_in[1];
    const float* an   = (const float*)d_in[2];
    const float* wgp  = (const float*)d_in[3];
    const float* wl   = (const float*)d_in[4];
    const float* bl   = (const float*)d_in[5];
    const float* wu   = (const float*)d_in[6];
    const float* bu   = (const float*)d_in[7];
    const float* aact = (const float*)d_in[8];
    const float* bact = (const float*)d_in[9];
    const float* wd   = (const float*)d_in[10];
    const float* bd   = (const float*)d_in[11];

    int Btot = in_sizes[0] / 128;
    int grid = (Btot + TB - 1) / TB;
    size_t smem = SMEM_FLOATS * sizeof(float);
    cudaFuncSetAttribute(ga_kernel, cudaFuncAttributeMaxDynamicSharedMemorySize, (int)smem);
    ga_kernel<<<grid, NT, smem>>>(x, wr, an, wgp, wl, bl, wu, bu, aact, bact, wd, bd,
                                  (float*)d_out, Btot);
}